// round 16
// baseline (speedup 1.0000x reference)
#include <cuda_runtime.h>
#include <cstdint>

#define KNN 64
#define WPB 16
#define THREADS 512
#define QPB (WPB * 2)            // 32 queries per block
#define POOLCAP 128
#define PCAP2 132                // POOLCAP + 4 pad entries (uint4-aligned)
#define FULLMASK 0xFFFFFFFFu
#define NMAX 32768

typedef unsigned long long u64;

// Global negated SoA scratch (filled by transpose_kernel each launch).
__device__ float g_nx[NMAX], g_ny[NMAX], g_nz[NMAX], g_nw[NMAX];

// Packed 2xfp32 ops (sm_100+). ptxas never emits these from C++ — PTX only.
#define PACK2(out, lo, hi) \
    asm("mov.b64 %0, {%1, %2};" : "=l"(out) : "f"(lo), "f"(hi))
#define ADD2(out, a, b) \
    asm("add.rn.f32x2 %0, %1, %2;" : "=l"(out) : "l"(a), "l"(b))
#define MUL2(out, a, b) \
    asm("mul.rn.f32x2 %0, %1, %2;" : "=l"(out) : "l"(a), "l"(b))
#define FMA2(out, a, b, c) \
    asm("fma.rn.f32x2 %0, %1, %2, %3;" : "=l"(out) : "l"(a), "l"(b), "l"(c))

__device__ __forceinline__ unsigned umin_(unsigned a, unsigned b) { return a < b ? a : b; }
__device__ __forceinline__ unsigned umax_(unsigned a, unsigned b) { return a > b ? a : b; }

// Diff-form packed distance: d2 = (q-c).(q-c), c pre-negated.
// Op order w,z,y,x matches the scalar fallback exactly. d2 >= 0 always.
#define DIST2(dout, CX, CY, CZ, CW, QX, QY, QZ, QW) do {                   \
    u64 _dx, _dy, _dz, _dw;                                                \
    ADD2(_dx, QX, CX); ADD2(_dy, QY, CY);                                  \
    ADD2(_dz, QZ, CZ); ADD2(_dw, QW, CW);                                  \
    MUL2(dout, _dw, _dw); FMA2(dout, _dz, _dz, dout);                      \
    FMA2(dout, _dy, _dy, dout); FMA2(dout, _dx, _dx, dout);                \
} while (0)

// Insert packed pair (v0,v1) into sorted pair-slot (s0 <= s1): 6 IMNMX.
#define INS2(s0, s1, v0, v1) do {                                          \
    unsigned _lo = umin_(v0, v1), _hi = umax_(v0, v1);                     \
    s1 = umin_(umax_(s0, _lo), umin_(s1, _hi));                            \
    s0 = umin_(s0, _lo);                                                   \
} while (0)

// tau = (64th smallest of the warp's 128 collected bit-values) + 1.
// Collected set is a subset of all candidate d2 bits -> tau upper-bounds the
// true 64th-smallest distance, so the filter keeps the whole top-64.
__device__ __forceinline__ unsigned find_tau(unsigned T00, unsigned T01,
                                             unsigned T10, unsigned T11)
{
    unsigned lo = __reduce_min_sync(FULLMASK, umin_(T00, T10));       // count==0
    unsigned hi = __reduce_max_sync(FULLMASK, umax_(T01, T11)) + 1u;  // count==128
    while (lo + 1u < hi) {
        unsigned mid = lo + ((hi - lo) >> 1);
        unsigned c4 = (unsigned)(T00 < mid) + (unsigned)(T01 < mid)
                    + (unsigned)(T10 < mid) + (unsigned)(T11 < mid);
        c4 = __reduce_add_sync(FULLMASK, c4);
        if (c4 >= 64u) hi = mid; else lo = mid;
    }
    return hi;
}

// Exact rank scatter over split pools. Ranks by u32 d2-bits (uint4 inner
// loop); exactness verified by the rank-sum permutation check, with an exact
// (d2, idx) lexicographic re-rank on the (rare) tie.
template <int R>
__device__ __forceinline__ void rank_scatter(const unsigned* pD, const unsigned* pI,
                                             int cnt,
                                             float* out_idx, float* out_dist,
                                             size_t obase, int gbase, int lane)
{
    unsigned kd[R], ki[R];
    int r[R];
#pragma unroll
    for (int i = 0; i < R; i++) {
        int e = lane + 32 * i;
        bool v = e < cnt;
        kd[i] = v ? pD[e] : 0xFFFFFFFFu;
        ki[i] = v ? pI[e] : 0u;
        r[i] = 0;
    }
    const int cntP = (cnt + 3) & ~3;
    for (int j = 0; j < cntP; j += 4) {
        uint4 d = *reinterpret_cast<const uint4*>(pD + j);   // LDS.128 broadcast
#pragma unroll
        for (int i = 0; i < R; i++) {
            r[i] += (int)(d.x < kd[i]) + (int)(d.y < kd[i])
                  + (int)(d.z < kd[i]) + (int)(d.w < kd[i]);
        }
    }
    int s = 0;
#pragma unroll
    for (int i = 0; i < R; i++)
        if (lane + 32 * i < cnt) s += r[i];
    s = __reduce_add_sync(FULLMASK, s);
    if (s != (cnt * (cnt - 1)) / 2) {
#pragma unroll
        for (int i = 0; i < R; i++) r[i] = 0;
        for (int j = 0; j < cnt; j++) {
            unsigned dj = pD[j], ij = pI[j];
#pragma unroll
            for (int i = 0; i < R; i++)
                r[i] += (int)((dj < kd[i]) || (dj == kd[i] && ij < ki[i]));
        }
    }
#pragma unroll
    for (int i = 0; i < R; i++) {
        int e = lane + 32 * i;
        if (e < cnt && r[i] < KNN) {
            out_idx [obase + r[i]] = (float)((int)ki[i] + gbase);
            out_dist[obase + r[i]] = __uint_as_float(kd[i]);
        }
    }
}

// Exact bound-tournament (pathological overflow only; smem, scalar diff-form).
__device__ __forceinline__ void exact_tournament(const float* nx, const float* ny,
                                                 const float* nz, const float* nw,
                                                 float qx, float qy, float qz, float qw,
                                                 int S,
                                                 float* out_idx, float* out_dist,
                                                 size_t obase, int gbase, int lane)
{
    u64 bound = 0ULL;
    const int iters = S >> 5;
#pragma unroll 1
    for (int kk = 0; kk < KNN; kk++) {
        u64 best = ~0ULL;
        for (int m = 0; m < iters; m++) {
            const int j = (m << 5) + lane;
            float dx = qx + nx[j], dy = qy + ny[j], dz = qz + nz[j], dw = qw + nw[j];
            float d2 = fmaf(dx, dx, fmaf(dy, dy, fmaf(dz, dz, dw * dw)));
            u64 key = (((u64)__float_as_uint(d2)) << 32) | (unsigned)j;
            if (key >= bound && key < best) best = key;
        }
        unsigned hb = (unsigned)(best >> 32);
        unsigned mh = __reduce_min_sync(FULLMASK, hb);
        unsigned lb = (hb == mh) ? (unsigned)best : 0xFFFFFFFFu;
        unsigned ml = __reduce_min_sync(FULLMASK, lb);
        if (lane == 0) {
            out_idx [obase + kk] = (float)((int)ml + gbase);
            out_dist[obase + kk] = __uint_as_float(mh);
        }
        bound = ((((u64)mh) << 32) | ml) + 1ULL;
    }
}

__global__ void transpose_kernel(const float4* __restrict__ coords, int N)
{
    int i = blockIdx.x * blockDim.x + threadIdx.x;
    if (i < N) {
        float4 c = coords[i];
        g_nx[i] = -c.x; g_ny[i] = -c.y; g_nz[i] = -c.z; g_nw[i] = -c.w;
    }
}

__global__ void __launch_bounds__(THREADS, 2)
knn_split_kernel(const float4* __restrict__ coords,
                 float* __restrict__ out_idx,
                 float* __restrict__ out_dist,
                 int S)
{
    extern __shared__ unsigned char smem_raw[];
    float* nx = reinterpret_cast<float*>(smem_raw);
    float* ny = nx + S;
    float* nz = ny + S;
    float* nw = nz + S;
    int* cntBase = reinterpret_cast<int*>(smem_raw + (size_t)S * 4 * sizeof(float));
    unsigned* poolD = reinterpret_cast<unsigned*>(cntBase + WPB * 2);
    unsigned* poolI = poolD + (size_t)WPB * 2 * PCAP2;

    const int tid  = threadIdx.x;
    const int warp = tid >> 5;
    const int lane = tid & 31;

    const int bps = S / QPB;
    const int seg = blockIdx.x / bps;
    const int qloc = (blockIdx.x % bps) * QPB + warp * 2;   // queries qloc, qloc+1
    const int gbase = seg * S;

    // ---- stage negated SoA coords into smem (pass-1 + fallback path) ----
    const float4* segc = coords + (size_t)gbase;
    for (int i = tid; i < S; i += THREADS) {
        float4 c = segc[i];
        nx[i] = -c.x; ny[i] = -c.y; nz[i] = -c.z; nw[i] = -c.w;
    }
    if (tid < WPB * 2) cntBase[tid] = 0;
    __syncthreads();

    const float qax = -nx[qloc],     qay = -ny[qloc],     qaz = -nz[qloc],     qaw = -nw[qloc];
    const float qbx = -nx[qloc + 1], qby = -ny[qloc + 1], qbz = -nz[qloc + 1], qbw = -nw[qloc + 1];

    u64 qAx, qAy, qAz, qAw, qBx, qBy, qBz, qBw;
    PACK2(qAx, qax, qax); PACK2(qAy, qay, qay); PACK2(qAz, qaz, qaz); PACK2(qAw, qaw, qaw);
    PACK2(qBx, qbx, qbx); PACK2(qBy, qby, qby); PACK2(qBz, qbz, qbz); PACK2(qBw, qbw, qbw);

    const int iters = S >> 7;               // 32 iters, 4 candidates/lane/iter
    const int lane4 = lane << 2;

    // ---- pass 1 (smem): INS2 top-2 per pair-stream -> exact tau bound ----
    unsigned A00 = ~0u, A01 = ~0u, A10 = ~0u, A11 = ~0u;
    unsigned B00 = ~0u, B01 = ~0u, B10 = ~0u, B11 = ~0u;

#pragma unroll 2
    for (int m = 0; m < iters; m++) {
        const int j = (m << 7) + lane4;
        ulonglong2 cx = *reinterpret_cast<const ulonglong2*>(nx + j);
        ulonglong2 cy = *reinterpret_cast<const ulonglong2*>(ny + j);
        ulonglong2 cz = *reinterpret_cast<const ulonglong2*>(nz + j);
        ulonglong2 cw = *reinterpret_cast<const ulonglong2*>(nw + j);

        u64 dA0, dA1, dB0, dB1;
        DIST2(dA0, cx.x, cy.x, cz.x, cw.x, qAx, qAy, qAz, qAw);
        DIST2(dA1, cx.y, cy.y, cz.y, cw.y, qAx, qAy, qAz, qAw);
        DIST2(dB0, cx.x, cy.x, cz.x, cw.x, qBx, qBy, qBz, qBw);
        DIST2(dB1, cx.y, cy.y, cz.y, cw.y, qBx, qBy, qBz, qBw);

        INS2(A00, A01, (unsigned)dA0, (unsigned)(dA0 >> 32));
        INS2(A10, A11, (unsigned)dA1, (unsigned)(dA1 >> 32));
        INS2(B00, B01, (unsigned)dB0, (unsigned)(dB0 >> 32));
        INS2(B10, B11, (unsigned)dB1, (unsigned)(dB1 >> 32));
    }

    const unsigned tauA = find_tau(A00, A01, A10, A11);
    const unsigned tauB = find_tau(B00, B01, B10, B11);

    // ---- pass 2 (GLOBAL SoA, L2-resident): filter + append to smem pools ----
    unsigned* pDA = poolD + (size_t)(warp * 2) * PCAP2;
    unsigned* pDB = pDA + PCAP2;
    unsigned* pIA = poolI + (size_t)(warp * 2) * PCAP2;
    unsigned* pIB = pIA + PCAP2;
    int* cntA = cntBase + warp * 2;
    int* cntB = cntA + 1;

    const float* gx = g_nx + gbase;
    const float* gy = g_ny + gbase;
    const float* gz = g_nz + gbase;
    const float* gw = g_nw + gbase;

#pragma unroll 2
    for (int m = 0; m < iters; m++) {
        const int j = (m << 7) + lane4;
        ulonglong2 cx = *reinterpret_cast<const ulonglong2*>(gx + j);
        ulonglong2 cy = *reinterpret_cast<const ulonglong2*>(gy + j);
        ulonglong2 cz = *reinterpret_cast<const ulonglong2*>(gz + j);
        ulonglong2 cw = *reinterpret_cast<const ulonglong2*>(gw + j);

        u64 dA0, dA1, dB0, dB1;
        DIST2(dA0, cx.x, cy.x, cz.x, cw.x, qAx, qAy, qAz, qAw);
        DIST2(dA1, cx.y, cy.y, cz.y, cw.y, qAx, qAy, qAz, qAw);
        DIST2(dB0, cx.x, cy.x, cz.x, cw.x, qBx, qBy, qBz, qBw);
        DIST2(dB1, cx.y, cy.y, cz.y, cw.y, qBx, qBy, qBz, qBw);

        unsigned a0 = (unsigned)dA0, a1 = (unsigned)(dA0 >> 32);
        unsigned a2 = (unsigned)dA1, a3 = (unsigned)(dA1 >> 32);
        unsigned b0 = (unsigned)dB0, b1 = (unsigned)(dB0 >> 32);
        unsigned b2 = (unsigned)dB1, b3 = (unsigned)(dB1 >> 32);

        if (a0 < tauA) { int p = atomicAdd(cntA, 1);
            if (p < POOLCAP) { pDA[p] = a0; pIA[p] = (unsigned)(j + 0); } }
        if (a1 < tauA) { int p = atomicAdd(cntA, 1);
            if (p < POOLCAP) { pDA[p] = a1; pIA[p] = (unsigned)(j + 1); } }
        if (a2 < tauA) { int p = atomicAdd(cntA, 1);
            if (p < POOLCAP) { pDA[p] = a2; pIA[p] = (unsigned)(j + 2); } }
        if (a3 < tauA) { int p = atomicAdd(cntA, 1);
            if (p < POOLCAP) { pDA[p] = a3; pIA[p] = (unsigned)(j + 3); } }
        if (b0 < tauB) { int p = atomicAdd(cntB, 1);
            if (p < POOLCAP) { pDB[p] = b0; pIB[p] = (unsigned)(j + 0); } }
        if (b1 < tauB) { int p = atomicAdd(cntB, 1);
            if (p < POOLCAP) { pDB[p] = b1; pIB[p] = (unsigned)(j + 1); } }
        if (b2 < tauB) { int p = atomicAdd(cntB, 1);
            if (p < POOLCAP) { pDB[p] = b2; pIB[p] = (unsigned)(j + 2); } }
        if (b3 < tauB) { int p = atomicAdd(cntB, 1);
            if (p < POOLCAP) { pDB[p] = b3; pIB[p] = (unsigned)(j + 3); } }
    }
    __syncwarp();

    const int cA = *cntA;
    const int cB = *cntB;

    // pad pools to a uint4 boundary with MAX keys (never beat real entries)
    if (lane < 4) {
        if (cA <= POOLCAP) pDA[cA + lane] = 0xFFFFFFFFu;
        if (cB <= POOLCAP) pDB[cB + lane] = 0xFFFFFFFFu;
    }
    __syncwarp();

    // ---- exact rank scatter to output, per query ----
    const size_t obA = (size_t)(gbase + qloc) * KNN;
    const size_t obB = obA + KNN;

    if (cA <= 96)           rank_scatter<3>(pDA, pIA, cA, out_idx, out_dist, obA, gbase, lane);
    else if (cA <= POOLCAP) rank_scatter<4>(pDA, pIA, cA, out_idx, out_dist, obA, gbase, lane);
    else exact_tournament(nx, ny, nz, nw, qax, qay, qaz, qaw, S,
                          out_idx, out_dist, obA, gbase, lane);

    if (cB <= 96)           rank_scatter<3>(pDB, pIB, cB, out_idx, out_dist, obB, gbase, lane);
    else if (cB <= POOLCAP) rank_scatter<4>(pDB, pIB, cB, out_idx, out_dist, obB, gbase, lane);
    else exact_tournament(nx, ny, nz, nw, qbx, qby, qbz, qbw, S,
                          out_idx, out_dist, obB, gbase, lane);
}

extern "C" void kernel_launch(void* const* d_in, const int* in_sizes, int n_in,
                              void* d_out, int out_size)
{
    // metadata order: K (scalar), coordinates [N*4 f32], row_splits [B+1 i32]
    const float4* coords = (const float4*)d_in[1];
    const int n_coord_floats = in_sizes[1];
    const int B = in_sizes[2] - 1;
    const int N = n_coord_floats / 4;   // D = 4
    const int S = N / B;                // equal-sized segments (4096)

    float* out = (float*)d_out;
    float* out_idx  = out;
    float* out_dist = out + (size_t)N * KNN;

    // Pre-pass: negated SoA planes into L2-resident global scratch.
    transpose_kernel<<<(N + 255) / 256, 256>>>(coords, N);

    size_t smem = (size_t)S * 4 * sizeof(float)
                + (size_t)WPB * 2 * sizeof(int)
                + (size_t)WPB * 2 * PCAP2 * 2 * sizeof(unsigned);

    cudaFuncSetAttribute(knn_split_kernel,
                         cudaFuncAttributeMaxDynamicSharedMemorySize, (int)smem);
    cudaFuncSetAttribute(knn_split_kernel,
                         cudaFuncAttributePreferredSharedMemoryCarveout, 100);

    dim3 block(THREADS);
    dim3 grid(N / QPB);
    knn_split_kernel<<<grid, block, smem>>>(coords, out_idx, out_dist, S);
}